// round 3
// baseline (speedup 1.0000x reference)
#include <cuda_runtime.h>
#include <cuda_bf16.h>

// Graph attention layer:
//   Q=xWq, K=xWk, V=xWv
//   score_e = <Q[recv], K[send]> / sqrt(D)
//   alpha_e = segment softmax over incoming edges of recv
//   out = x + segment_sum(alpha * V[send]) @ Wo
//
// Max-free softmax: scores ~ N(0,1) after scaling (max ~5 over 1.6M), so
// exp(score) cannot overflow and normalization is mathematically identical.
//
// edge_index dtype: reference declares int64 but JAX without x64 produces
// int32. We sniff the dtype on-device (deterministic) and convert indices to
// int arrays either way.

#define N_NODES 100000
#define E_EDGES 1600000
#define DIM 32

// Scratch (allocation-free rule: __device__ globals)
__device__ float g_Q[N_NODES * DIM];
__device__ float g_K[N_NODES * DIM];
__device__ float g_V[N_NODES * DIM];
__device__ float g_num[N_NODES * DIM];   // unnormalized weighted V sum
__device__ float g_Z[N_NODES];           // softmax denominator
__device__ int   g_s[E_EDGES];           // sender indices (int32)
__device__ int   g_r[E_EDGES];           // receiver indices (int32)
__device__ int   g_is64;                 // 1 if edge_index is int64

// ---------------------------------------------------------------------------
// Kernel 0a: dtype sniffer. If edge_index is int64, first 32 words are all in
// [0, N). If int32, each int64 word combines two int32s -> huge unless the
// odd element is 0 (p ~ 1e-5 per word; all 32 ~ impossible).
// ---------------------------------------------------------------------------
__global__ void sniff_kernel(const void* __restrict__ ei_raw)
{
    const long long* w = (const long long*)ei_raw;
    int is64 = 1;
    for (int i = 0; i < 32; i++) {
        long long v = w[i];
        if (v < 0 || v >= N_NODES) { is64 = 0; break; }
    }
    g_is64 = is64;
}

// ---------------------------------------------------------------------------
// Kernel 0b: convert indices into int arrays (branch is uniform on g_is64).
// ---------------------------------------------------------------------------
__global__ __launch_bounds__(256) void convert_kernel(const void* __restrict__ ei_raw)
{
    int i = blockIdx.x * blockDim.x + threadIdx.x;
    if (i >= E_EDGES) return;
    if (g_is64) {
        const long long* e = (const long long*)ei_raw;
        g_s[i] = (int)e[i];
        g_r[i] = (int)e[E_EDGES + i];
    } else {
        const int* e = (const int*)ei_raw;
        g_s[i] = e[i];
        g_r[i] = e[E_EDGES + i];
    }
}

// ---------------------------------------------------------------------------
// Kernel 1: Q/K/V projections, warp per node, lane = output dim.
// Also zero-initializes g_num / g_Z (deterministic per launch).
// ---------------------------------------------------------------------------
__global__ __launch_bounds__(256) void qkv_kernel(
    const float* __restrict__ x,
    const float* __restrict__ Wq,
    const float* __restrict__ Wk,
    const float* __restrict__ Wv)
{
    int warp = (blockIdx.x * blockDim.x + threadIdx.x) >> 5;
    int lane = threadIdx.x & 31;
    if (warp >= N_NODES) return;

    float xv = x[warp * DIM + lane];
    float q = 0.f, k = 0.f, v = 0.f;
#pragma unroll
    for (int j = 0; j < DIM; j++) {
        float xj = __shfl_sync(0xffffffffu, xv, j);
        q = fmaf(xj, Wq[j * DIM + lane], q);
        k = fmaf(xj, Wk[j * DIM + lane], k);
        v = fmaf(xj, Wv[j * DIM + lane], v);
    }
    g_Q[warp * DIM + lane] = q;
    g_K[warp * DIM + lane] = k;
    g_V[warp * DIM + lane] = v;
    g_num[warp * DIM + lane] = 0.f;
    if (lane == 0) g_Z[warp] = 0.f;
}

// ---------------------------------------------------------------------------
// Kernel 2: edge phase. Warp per edge, lane = dim.
//   score = sum(Q[r] * K[s]) * scale;  alpha = exp(score)
//   RED: g_Z[r] += alpha;  g_num[r][:] += alpha * V[s][:]
// All row accesses are 128B coalesced; atomics compile to RED (no return).
// ---------------------------------------------------------------------------
__global__ __launch_bounds__(256) void edge_kernel()
{
    int warp = (blockIdx.x * blockDim.x + threadIdx.x) >> 5;
    int lane = threadIdx.x & 31;
    if (warp >= E_EDGES) return;

    int s = g_s[warp];
    int r = g_r[warp];

    float p = g_Q[r * DIM + lane] * g_K[s * DIM + lane];
#pragma unroll
    for (int off = 16; off; off >>= 1)
        p += __shfl_xor_sync(0xffffffffu, p, off);

    const float scale = 0.1767766952966369f;  // 1/sqrt(32)
    float alpha = __expf(p * scale);

    if (lane == 0) atomicAdd(&g_Z[r], alpha);
    atomicAdd(&g_num[r * DIM + lane], alpha * g_V[s * DIM + lane]);
}

// ---------------------------------------------------------------------------
// Kernel 3: normalize, output projection, residual. Warp per node.
// ---------------------------------------------------------------------------
__global__ __launch_bounds__(256) void out_kernel(
    const float* __restrict__ x,
    const float* __restrict__ Wo,
    float* __restrict__ out)
{
    int warp = (blockIdx.x * blockDim.x + threadIdx.x) >> 5;
    int lane = threadIdx.x & 31;
    if (warp >= N_NODES) return;

    float o = g_num[warp * DIM + lane] / (g_Z[warp] + 1e-6f);
    float acc = x[warp * DIM + lane];
#pragma unroll
    for (int j = 0; j < DIM; j++) {
        float oj = __shfl_sync(0xffffffffu, o, j);
        acc = fmaf(oj, Wo[j * DIM + lane], acc);
    }
    out[warp * DIM + lane] = acc;
}

// ---------------------------------------------------------------------------
// Launch. Inputs (metadata order): x, edge_index, Wq, Wk, Wv, Wo.
// ---------------------------------------------------------------------------
extern "C" void kernel_launch(void* const* d_in, const int* in_sizes, int n_in,
                              void* d_out, int out_size)
{
    const float* x  = (const float*)d_in[0];
    const void*  ei = d_in[1];
    const float* Wq = (const float*)d_in[2];
    const float* Wk = (const float*)d_in[3];
    const float* Wv = (const float*)d_in[4];
    const float* Wo = (const float*)d_in[5];
    float* out = (float*)d_out;

    const int TPB = 256;
    const int WPB = TPB / 32;

    sniff_kernel<<<1, 1>>>(ei);
    convert_kernel<<<(E_EDGES + TPB - 1) / TPB, TPB>>>(ei);
    qkv_kernel<<<(N_NODES + WPB - 1) / WPB, TPB>>>(x, Wq, Wk, Wv);
    edge_kernel<<<(E_EDGES + WPB - 1) / WPB, TPB>>>();
    out_kernel<<<(N_NODES + WPB - 1) / WPB, TPB>>>(x, Wo, out);
}

// round 7
// speedup vs baseline: 1.2768x; 1.2768x over previous
#include <cuda_runtime.h>
#include <cuda_bf16.h>

// Graph attention layer:
//   Q=xWq, K=xWk, V=xWv
//   score_e = <Q[recv], K[send]> / sqrt(D)
//   alpha_e = segment softmax over incoming edges of recv
//   out = x + segment_sum(alpha * V[send]) @ Wo
//
// Max-free softmax: scores ~ N(0,1) after scaling (max ~5 over 1.6M), so
// exp(score) cannot overflow and normalization is mathematically identical.
//
// Edge phase layout: 4 edges per warp; each 8-lane group handles one edge,
// each lane holds 4 dims (float4). 3-shfl reduction + red.global.add.v4.f32.

#define N_NODES 100000
#define E_EDGES 1600000
#define DIM 32

// Scratch (allocation-free rule: __device__ globals)
__device__ float g_Q[N_NODES * DIM];
__device__ float g_K[N_NODES * DIM];
__device__ float g_V[N_NODES * DIM];
__device__ float g_num[N_NODES * DIM];   // unnormalized weighted V sum
__device__ float g_Z[N_NODES];           // softmax denominator
__device__ int2  g_sr[E_EDGES];          // packed (sender, receiver)

// ---------------------------------------------------------------------------
// Kernel 0: dtype sniff (per block, into shared) + index convert to int2.
// JAX without x64 silently emits int32 even though the reference says int64;
// if int64, the first 32 little-endian 8B words are all in [0,N) — if int32,
// the packed pairs exceed N with overwhelming probability.
// ---------------------------------------------------------------------------
__global__ __launch_bounds__(256) void convert_kernel(const void* __restrict__ ei_raw)
{
    __shared__ int s_is64;
    if (threadIdx.x == 0) {
        const long long* w = (const long long*)ei_raw;
        int is64 = 1;
        for (int i = 0; i < 32; i++) {
            long long v = w[i];
            if (v < 0 || v >= N_NODES) { is64 = 0; break; }
        }
        s_is64 = is64;
    }
    __syncthreads();

    int i = blockIdx.x * blockDim.x + threadIdx.x;
    if (i >= E_EDGES) return;
    int s, r;
    if (s_is64) {
        const long long* e = (const long long*)ei_raw;
        s = (int)e[i];
        r = (int)e[E_EDGES + i];
    } else {
        const int* e = (const int*)ei_raw;
        s = e[i];
        r = e[E_EDGES + i];
    }
    g_sr[i] = make_int2(s, r);
}

// ---------------------------------------------------------------------------
// Kernel 1: Q/K/V projections, warp per node, lane = output dim.
// Also zero-initializes g_num / g_Z (deterministic per launch).
// ---------------------------------------------------------------------------
__global__ __launch_bounds__(256) void qkv_kernel(
    const float* __restrict__ x,
    const float* __restrict__ Wq,
    const float* __restrict__ Wk,
    const float* __restrict__ Wv)
{
    int warp = (blockIdx.x * blockDim.x + threadIdx.x) >> 5;
    int lane = threadIdx.x & 31;
    if (warp >= N_NODES) return;

    float xv = x[warp * DIM + lane];
    float q = 0.f, k = 0.f, v = 0.f;
#pragma unroll
    for (int j = 0; j < DIM; j++) {
        float xj = __shfl_sync(0xffffffffu, xv, j);
        q = fmaf(xj, Wq[j * DIM + lane], q);
        k = fmaf(xj, Wk[j * DIM + lane], k);
        v = fmaf(xj, Wv[j * DIM + lane], v);
    }
    g_Q[warp * DIM + lane] = q;
    g_K[warp * DIM + lane] = k;
    g_V[warp * DIM + lane] = v;
    g_num[warp * DIM + lane] = 0.f;
    if (lane == 0) g_Z[warp] = 0.f;
}

// ---------------------------------------------------------------------------
// Kernel 2: edge phase. 4 edges/warp; 8 lanes x float4 per edge.
// ---------------------------------------------------------------------------
__global__ __launch_bounds__(256) void edge_kernel()
{
    int warp = (blockIdx.x * blockDim.x + threadIdx.x) >> 5;
    int l = threadIdx.x & 7;          // dim-quad within edge
    int e = warp * 4 + ((threadIdx.x & 31) >> 3);
    if (e >= E_EDGES) return;         // E % 4 == 0: warp-uniform exit

    int2 sr = g_sr[e];                // 8-lane broadcast load
    int s = sr.x, r = sr.y;

    const float4* Q4 = (const float4*)g_Q;
    const float4* K4 = (const float4*)g_K;
    const float4* V4 = (const float4*)g_V;

    float4 q = Q4[r * 8 + l];
    float4 k = K4[s * 8 + l];
    float p = q.x * k.x + q.y * k.y + q.z * k.z + q.w * k.w;
    p += __shfl_xor_sync(0xffffffffu, p, 1);
    p += __shfl_xor_sync(0xffffffffu, p, 2);
    p += __shfl_xor_sync(0xffffffffu, p, 4);

    const float scale = 0.1767766952966369f;   // 1/sqrt(32)
    float alpha = __expf(p * scale);

    float4 v = V4[s * 8 + l];
    float* dst = g_num + r * DIM + l * 4;      // 16B-aligned
    asm volatile("red.global.add.v4.f32 [%0], {%1,%2,%3,%4};"
                 :: "l"(dst),
                    "f"(alpha * v.x), "f"(alpha * v.y),
                    "f"(alpha * v.z), "f"(alpha * v.w)
                 : "memory");
    if (l == 0) atomicAdd(&g_Z[r], alpha);
}

// ---------------------------------------------------------------------------
// Kernel 3: normalize, output projection, residual. Warp per node.
// ---------------------------------------------------------------------------
__global__ __launch_bounds__(256) void out_kernel(
    const float* __restrict__ x,
    const float* __restrict__ Wo,
    float* __restrict__ out)
{
    int warp = (blockIdx.x * blockDim.x + threadIdx.x) >> 5;
    int lane = threadIdx.x & 31;
    if (warp >= N_NODES) return;

    float o = g_num[warp * DIM + lane] / (g_Z[warp] + 1e-6f);
    float acc = x[warp * DIM + lane];
#pragma unroll
    for (int j = 0; j < DIM; j++) {
        float oj = __shfl_sync(0xffffffffu, o, j);
        acc = fmaf(oj, Wo[j * DIM + lane], acc);
    }
    out[warp * DIM + lane] = acc;
}

// ---------------------------------------------------------------------------
// Launch. Inputs (metadata order): x, edge_index, Wq, Wk, Wv, Wo.
// ---------------------------------------------------------------------------
extern "C" void kernel_launch(void* const* d_in, const int* in_sizes, int n_in,
                              void* d_out, int out_size)
{
    const float* x  = (const float*)d_in[0];
    const void*  ei = d_in[1];
    const float* Wq = (const float*)d_in[2];
    const float* Wk = (const float*)d_in[3];
    const float* Wv = (const float*)d_in[4];
    const float* Wo = (const float*)d_in[5];
    float* out = (float*)d_out;

    const int TPB = 256;
    const int WPB = TPB / 32;

    int edge_warps  = (E_EDGES + 3) / 4;                 // 4 edges per warp
    int edge_blocks = (edge_warps + WPB - 1) / WPB;

    convert_kernel<<<(E_EDGES + TPB - 1) / TPB, TPB>>>(ei);
    qkv_kernel<<<(N_NODES + WPB - 1) / WPB, TPB>>>(x, Wq, Wk, Wv);
    edge_kernel<<<edge_blocks, TPB>>>();
    out_kernel<<<(N_NODES + WPB - 1) / WPB, TPB>>>(x, Wo, out);
}

// round 9
// speedup vs baseline: 2.2245x; 1.7422x over previous
#include <cuda_runtime.h>
#include <cuda_bf16.h>

// Graph attention layer, algebraically fused:
//   score_e = x[r]^T (Wq Wk^T) x[s] / sqrt(D)     (M = Wq Wk^T precomputed)
//   alpha_e = segment softmax over incoming edges of r (max-free; scores O(1))
//   num[r]  = seg_sum(alpha * (x @ Wv @ Wo)[s])   (Wvo = Wv Wo precomputed;
//                                                  valid because Z is a per-row
//                                                  scalar: (num/Z)@Wo = (num@Wo)/Z)
//   out     = x + num / (Z + 1e-6)                (pure elementwise)

#define N_NODES 100000
#define E_EDGES 1600000
#define DIM 32

// Scratch (allocation-free rule: __device__ globals)
__device__ float g_Q[N_NODES * DIM];     // x @ M
__device__ float g_VW[N_NODES * DIM];    // x @ Wvo
__device__ float g_num[N_NODES * DIM];   // unnormalized weighted VW sum
__device__ float g_Z[N_NODES];           // softmax denominator
__device__ int2  g_sr[E_EDGES];          // packed (sender, receiver)
__device__ float g_M[DIM * DIM];         // Wq @ Wk^T
__device__ float g_Wvo[DIM * DIM];       // Wv @ Wo

// ---------------------------------------------------------------------------
// Kernel P: fused weight products. One 32x32 block; trivial cost.
//   M[i][j]   = sum_k Wq[i][k] * Wk[j][k]
//   Wvo[i][j] = sum_k Wv[i][k] * Wo[k][j]
// ---------------------------------------------------------------------------
__global__ void prep_kernel(const float* __restrict__ Wq,
                            const float* __restrict__ Wk,
                            const float* __restrict__ Wv,
                            const float* __restrict__ Wo)
{
    int j = threadIdx.x, i = threadIdx.y;
    float m = 0.f, wv = 0.f;
#pragma unroll
    for (int k = 0; k < DIM; k++) {
        m  = fmaf(Wq[i * DIM + k], Wk[j * DIM + k], m);
        wv = fmaf(Wv[i * DIM + k], Wo[k * DIM + j], wv);
    }
    g_M[i * DIM + j] = m;
    g_Wvo[i * DIM + j] = wv;
}

// ---------------------------------------------------------------------------
// Kernel 0: dtype sniff (per block) + index convert to int2.
// JAX without x64 silently emits int32 even though the reference says int64.
// ---------------------------------------------------------------------------
__global__ __launch_bounds__(256) void convert_kernel(const void* __restrict__ ei_raw)
{
    __shared__ int s_is64;
    if (threadIdx.x == 0) {
        const long long* w = (const long long*)ei_raw;
        int is64 = 1;
        for (int i = 0; i < 32; i++) {
            long long v = w[i];
            if (v < 0 || v >= N_NODES) { is64 = 0; break; }
        }
        s_is64 = is64;
    }
    __syncthreads();

    int i = blockIdx.x * blockDim.x + threadIdx.x;
    if (i >= E_EDGES) return;
    int s, r;
    if (s_is64) {
        const long long* e = (const long long*)ei_raw;
        s = (int)e[i];
        r = (int)e[E_EDGES + i];
    } else {
        const int* e = (const int*)ei_raw;
        s = e[i];
        r = e[E_EDGES + i];
    }
    g_sr[i] = make_int2(s, r);
}

// ---------------------------------------------------------------------------
// Kernel 1: node projections Q' = x@M, VW = x@Wvo. Warp per node, lane = dim.
// Also zero-initializes g_num / g_Z.
// ---------------------------------------------------------------------------
__global__ __launch_bounds__(256) void proj_kernel(const float* __restrict__ x)
{
    int warp = (blockIdx.x * blockDim.x + threadIdx.x) >> 5;
    int lane = threadIdx.x & 31;
    if (warp >= N_NODES) return;

    float xv = x[warp * DIM + lane];
    float q = 0.f, vw = 0.f;
#pragma unroll
    for (int j = 0; j < DIM; j++) {
        float xj = __shfl_sync(0xffffffffu, xv, j);
        q  = fmaf(xj, g_M[j * DIM + lane], q);
        vw = fmaf(xj, g_Wvo[j * DIM + lane], vw);
    }
    g_Q[warp * DIM + lane] = q;
    g_VW[warp * DIM + lane] = vw;
    g_num[warp * DIM + lane] = 0.f;
    if (lane == 0) g_Z[warp] = 0.f;
}

// ---------------------------------------------------------------------------
// Kernel 2: edge phase. 4 edges/warp; 8 lanes x float4 per edge.
//   p = Q'[r] . x[s];  alpha = exp(p * scale)
//   RED: g_Z[r] += alpha;  g_num[r][:] += alpha * VW[s][:]
// ---------------------------------------------------------------------------
__global__ __launch_bounds__(256) void edge_kernel(const float* __restrict__ x)
{
    int warp = (blockIdx.x * blockDim.x + threadIdx.x) >> 5;
    int l = threadIdx.x & 7;          // dim-quad within edge
    int e = warp * 4 + ((threadIdx.x & 31) >> 3);
    if (e >= E_EDGES) return;         // E % 4 == 0: warp-uniform exit

    int2 sr = g_sr[e];                // 8-lane broadcast load
    int s = sr.x, r = sr.y;

    const float4* Q4 = (const float4*)g_Q;
    const float4* X4 = (const float4*)x;
    const float4* W4 = (const float4*)g_VW;

    float4 q = Q4[r * 8 + l];
    float4 k = X4[s * 8 + l];
    float p = q.x * k.x + q.y * k.y + q.z * k.z + q.w * k.w;
    p += __shfl_xor_sync(0xffffffffu, p, 1);
    p += __shfl_xor_sync(0xffffffffu, p, 2);
    p += __shfl_xor_sync(0xffffffffu, p, 4);

    const float scale = 0.1767766952966369f;   // 1/sqrt(32)
    float alpha = __expf(p * scale);

    float4 v = W4[s * 8 + l];
    float* dst = g_num + r * DIM + l * 4;      // 16B-aligned
    asm volatile("red.global.add.v4.f32 [%0], {%1,%2,%3,%4};"
                 :: "l"(dst),
                    "f"(alpha * v.x), "f"(alpha * v.y),
                    "f"(alpha * v.z), "f"(alpha * v.w)
                 : "memory");
    if (l == 0) atomicAdd(&g_Z[r], alpha);
}

// ---------------------------------------------------------------------------
// Kernel 3: out = x + num / (Z + 1e-6). Pure elementwise, float4 per thread.
// ---------------------------------------------------------------------------
__global__ __launch_bounds__(256) void out_kernel(
    const float* __restrict__ x,
    float* __restrict__ out)
{
    int t = blockIdx.x * blockDim.x + threadIdx.x;   // one float4 per thread
    if (t >= N_NODES * (DIM / 4)) return;
    int node = t >> 3;                               // 8 quads per node

    float inv = 1.0f / (g_Z[node] + 1e-6f);
    float4 n4 = ((const float4*)g_num)[t];
    float4 x4 = ((const float4*)x)[t];
    float4 o;
    o.x = fmaf(n4.x, inv, x4.x);
    o.y = fmaf(n4.y, inv, x4.y);
    o.z = fmaf(n4.z, inv, x4.z);
    o.w = fmaf(n4.w, inv, x4.w);
    ((float4*)out)[t] = o;
}

// ---------------------------------------------------------------------------
// Launch. Inputs (metadata order): x, edge_index, Wq, Wk, Wv, Wo.
// ---------------------------------------------------------------------------
extern "C" void kernel_launch(void* const* d_in, const int* in_sizes, int n_in,
                              void* d_out, int out_size)
{
    const float* x  = (const float*)d_in[0];
    const void*  ei = d_in[1];
    const float* Wq = (const float*)d_in[2];
    const float* Wk = (const float*)d_in[3];
    const float* Wv = (const float*)d_in[4];
    const float* Wo = (const float*)d_in[5];
    float* out = (float*)d_out;

    const int TPB = 256;
    const int WPB = TPB / 32;

    int edge_warps  = (E_EDGES + 3) / 4;
    int edge_blocks = (edge_warps + WPB - 1) / WPB;
    int quads       = N_NODES * (DIM / 4);

    prep_kernel<<<1, dim3(32, 32)>>>(Wq, Wk, Wv, Wo);
    convert_kernel<<<(E_EDGES + TPB - 1) / TPB, TPB>>>(ei);
    proj_kernel<<<(N_NODES + WPB - 1) / WPB, TPB>>>(x);
    edge_kernel<<<edge_blocks, TPB>>>(x);
    out_kernel<<<(quads + TPB - 1) / TPB, TPB>>>(x, out);
}

// round 14
// speedup vs baseline: 2.3794x; 1.0697x over previous
#include <cuda_runtime.h>
#include <cuda_bf16.h>

// Graph attention layer, algebraically fused:
//   score_e = x[r]^T (Wq Wk^T) x[s] / sqrt(D)     (M = Wq Wk^T precomputed)
//   alpha_e = segment softmax over incoming edges of r (max-free; scores O(1))
//   num[r]  = seg_sum(alpha * (x @ Wv @ Wo)[s])   (Wvo = Wv Wo precomputed;
//                                                  Z is a per-row scalar so
//                                                  (num/Z)@Wo = (num@Wo)/Z)
//   out     = x + num / (Z + 1e-6)                (pure elementwise)
//
// Edge kernel reads edge_index RAW (no repack pass): dtype sniffed once in
// prep (JAX without x64 silently emits int32 despite the int64 annotation),
// uniform branch per warp. 8 edges/warp: each 8-lane group handles 2 edges
// for 2-way ILP on gathers; lane holds 4 dims (float4).

#define N_NODES 100000
#define E_EDGES 1600000
#define DIM 32

// Scratch (allocation-free rule: __device__ globals)
__device__ float g_Q[N_NODES * DIM];     // x @ M
__device__ float g_VW[N_NODES * DIM];    // x @ Wvo
__device__ float g_num[N_NODES * DIM];   // unnormalized weighted VW sum
__device__ float g_Z[N_NODES];           // softmax denominator
__device__ float g_M[DIM * DIM];         // Wq @ Wk^T
__device__ float g_Wvo[DIM * DIM];       // Wv @ Wo
__device__ int   g_is64;                 // edge_index dtype flag

// ---------------------------------------------------------------------------
// Kernel P: fused weight products + dtype sniff. One 32x32 block.
//   M[i][j]   = sum_k Wq[i][k] * Wk[j][k]
//   Wvo[i][j] = sum_k Wv[i][k] * Wo[k][j]
// Sniff: if edge_index is int64, the first 32 8-byte words are all in [0,N);
// if int32, packed pairs exceed N with overwhelming probability.
// ---------------------------------------------------------------------------
__global__ void prep_kernel(const float* __restrict__ Wq,
                            const float* __restrict__ Wk,
                            const float* __restrict__ Wv,
                            const float* __restrict__ Wo,
                            const void* __restrict__ ei_raw)
{
    int j = threadIdx.x, i = threadIdx.y;
    float m = 0.f, wv = 0.f;
#pragma unroll
    for (int k = 0; k < DIM; k++) {
        m  = fmaf(Wq[i * DIM + k], Wk[j * DIM + k], m);
        wv = fmaf(Wv[i * DIM + k], Wo[k * DIM + j], wv);
    }
    g_M[i * DIM + j] = m;
    g_Wvo[i * DIM + j] = wv;

    if (i == 0) {  // warp 0: parallel sniff + ballot
        long long v = ((const long long*)ei_raw)[j];
        unsigned ok = __ballot_sync(0xffffffffu, v >= 0 && v < N_NODES);
        if (j == 0) g_is64 = (ok == 0xffffffffu);
    }
}

// ---------------------------------------------------------------------------
// Kernel 1: node projections Q' = x@M, VW = x@Wvo. Warp per node, lane = dim.
// Also zero-initializes g_num / g_Z.
// ---------------------------------------------------------------------------
__global__ __launch_bounds__(256) void proj_kernel(const float* __restrict__ x)
{
    int warp = (blockIdx.x * blockDim.x + threadIdx.x) >> 5;
    int lane = threadIdx.x & 31;
    if (warp >= N_NODES) return;

    float xv = x[warp * DIM + lane];
    float q = 0.f, vw = 0.f;
#pragma unroll
    for (int j = 0; j < DIM; j++) {
        float xj = __shfl_sync(0xffffffffu, xv, j);
        q  = fmaf(xj, g_M[j * DIM + lane], q);
        vw = fmaf(xj, g_Wvo[j * DIM + lane], vw);
    }
    g_Q[warp * DIM + lane] = q;
    g_VW[warp * DIM + lane] = vw;
    g_num[warp * DIM + lane] = 0.f;
    if (lane == 0) g_Z[warp] = 0.f;
}

// ---------------------------------------------------------------------------
// Kernel 2: edge phase. 8 edges/warp: 4 groups of 8 lanes, 2 edges per group.
//   p = Q'[r] . x[s];  alpha = exp(p * scale)
//   RED: g_Z[r] += alpha;  g_num[r][:] += alpha * VW[s][:]
// Indices read raw with a uniform dtype branch; pairs are even-aligned so
// int2 / longlong2 vector loads apply.
// ---------------------------------------------------------------------------
__global__ __launch_bounds__(256) void edge_kernel(const float* __restrict__ x,
                                                   const void* __restrict__ ei_raw)
{
    int warp = (blockIdx.x * blockDim.x + threadIdx.x) >> 5;
    int lane = threadIdx.x & 31;
    int l = lane & 7;                     // dim-quad within edge
    int e0 = warp * 8 + (lane >> 3) * 2;  // this group's edge pair (even)
    if (e0 >= E_EDGES) return;            // E % 8 == 0: warp-uniform exit

    int s0, r0, s1, r1;
    if (g_is64) {
        const longlong2* S = (const longlong2*)ei_raw;
        longlong2 sp = S[e0 >> 1];
        longlong2 rp = S[(E_EDGES + e0) >> 1];
        s0 = (int)sp.x; s1 = (int)sp.y;
        r0 = (int)rp.x; r1 = (int)rp.y;
    } else {
        const int2* S = (const int2*)ei_raw;
        int2 sp = S[e0 >> 1];
        int2 rp = S[(E_EDGES + e0) >> 1];
        s0 = sp.x; s1 = sp.y;
        r0 = rp.x; r1 = rp.y;
    }

    const float4* Q4 = (const float4*)g_Q;
    const float4* X4 = (const float4*)x;
    const float4* W4 = (const float4*)g_VW;

    // Issue both edges' gathers before consuming either (2-way MLP).
    float4 q0 = Q4[r0 * 8 + l];
    float4 k0 = X4[s0 * 8 + l];
    float4 q1 = Q4[r1 * 8 + l];
    float4 k1 = X4[s1 * 8 + l];

    float p0 = q0.x * k0.x + q0.y * k0.y + q0.z * k0.z + q0.w * k0.w;
    float p1 = q1.x * k1.x + q1.y * k1.y + q1.z * k1.z + q1.w * k1.w;
#pragma unroll
    for (int off = 1; off <= 4; off <<= 1) {
        p0 += __shfl_xor_sync(0xffffffffu, p0, off);
        p1 += __shfl_xor_sync(0xffffffffu, p1, off);
    }

    const float scale = 0.1767766952966369f;   // 1/sqrt(32)
    float a0 = __expf(p0 * scale);
    float a1 = __expf(p1 * scale);

    float4 v0 = W4[s0 * 8 + l];
    float4 v1 = W4[s1 * 8 + l];

    float* dst0 = g_num + r0 * DIM + l * 4;    // 16B-aligned
    asm volatile("red.global.add.v4.f32 [%0], {%1,%2,%3,%4};"
                 :: "l"(dst0),
                    "f"(a0 * v0.x), "f"(a0 * v0.y),
                    "f"(a0 * v0.z), "f"(a0 * v0.w) : "memory");
    float* dst1 = g_num + r1 * DIM + l * 4;
    asm volatile("red.global.add.v4.f32 [%0], {%1,%2,%3,%4};"
                 :: "l"(dst1),
                    "f"(a1 * v1.x), "f"(a1 * v1.y),
                    "f"(a1 * v1.z), "f"(a1 * v1.w) : "memory");
    if (l == 0) {
        atomicAdd(&g_Z[r0], a0);
        atomicAdd(&g_Z[r1], a1);
    }
}

// ---------------------------------------------------------------------------
// Kernel 3: out = x + num / (Z + 1e-6). Pure elementwise, float4 per thread.
// ---------------------------------------------------------------------------
__global__ __launch_bounds__(256) void out_kernel(
    const float* __restrict__ x,
    float* __restrict__ out)
{
    int t = blockIdx.x * blockDim.x + threadIdx.x;   // one float4 per thread
    if (t >= N_NODES * (DIM / 4)) return;
    int node = t >> 3;                               // 8 quads per node

    float inv = 1.0f / (g_Z[node] + 1e-6f);
    float4 n4 = ((const float4*)g_num)[t];
    float4 x4 = ((const float4*)x)[t];
    float4 o;
    o.x = fmaf(n4.x, inv, x4.x);
    o.y = fmaf(n4.y, inv, x4.y);
    o.z = fmaf(n4.z, inv, x4.z);
    o.w = fmaf(n4.w, inv, x4.w);
    ((float4*)out)[t] = o;
}

// ---------------------------------------------------------------------------
// Launch. Inputs (metadata order): x, edge_index, Wq, Wk, Wv, Wo.
// ---------------------------------------------------------------------------
extern "C" void kernel_launch(void* const* d_in, const int* in_sizes, int n_in,
                              void* d_out, int out_size)
{
    const float* x  = (const float*)d_in[0];
    const void*  ei = d_in[1];
    const float* Wq = (const float*)d_in[2];
    const float* Wk = (const float*)d_in[3];
    const float* Wv = (const float*)d_in[4];
    const float* Wo = (const float*)d_in[5];
    float* out = (float*)d_out;

    const int TPB = 256;
    const int WPB = TPB / 32;

    int edge_warps  = (E_EDGES + 7) / 8;                 // 8 edges per warp
    int edge_blocks = (edge_warps + WPB - 1) / WPB;
    int quads       = N_NODES * (DIM / 4);

    prep_kernel<<<1, dim3(32, 32)>>>(Wq, Wk, Wv, Wo, ei);
    proj_kernel<<<(N_NODES + WPB - 1) / WPB, TPB>>>(x);
    edge_kernel<<<edge_blocks, TPB>>>(x, ei);
    out_kernel<<<(quads + TPB - 1) / TPB, TPB>>>(x, out);
}

// round 15
// speedup vs baseline: 2.5854x; 1.0866x over previous
#include <cuda_runtime.h>
#include <cuda_bf16.h>

// Graph attention layer, algebraically fused:
//   score_e = x[r]^T (Wq Wk^T) x[s] / sqrt(D)     (M = Wq Wk^T precomputed)
//   alpha_e = segment softmax over incoming edges of r (max-free; scores O(1))
//   num[r]  = seg_sum(alpha * (x @ Wv @ Wo)[s])   (Wvo = Wv Wo precomputed;
//                                                  Z is a per-row scalar so
//                                                  (num/Z)@Wo = (num@Wo)/Z)
//   out     = x + num / (Z + 1e-6)                (pure elementwise)
//
// proj: 4 nodes/warp, 8 lanes/node, segmented shfl (width=8) broadcasts x[j]
// to all 4 node-groups in one instruction; float4 weight loads (L1-resident).
// edge: 8 edges/warp (2 per 8-lane group) with raw-dtype index reads.

#define N_NODES 100000
#define E_EDGES 1600000
#define DIM 32

// Scratch (allocation-free rule: __device__ globals)
__device__ float g_Q[N_NODES * DIM];     // x @ M
__device__ float g_VW[N_NODES * DIM];    // x @ Wvo
__device__ float g_num[N_NODES * DIM];   // unnormalized weighted VW sum
__device__ float g_Z[N_NODES];           // softmax denominator
__device__ float g_M[DIM * DIM];         // Wq @ Wk^T
__device__ float g_Wvo[DIM * DIM];       // Wv @ Wo
__device__ int   g_is64;                 // edge_index dtype flag

// ---------------------------------------------------------------------------
// Kernel P: fused weight products + dtype sniff. One 32x32 block.
//   M[i][j]   = sum_k Wq[i][k] * Wk[j][k]
//   Wvo[i][j] = sum_k Wv[i][k] * Wo[k][j]
// Sniff: int64 edge_index => first 32 8-byte words all in [0,N); int32 packed
// pairs exceed N with overwhelming probability (JAX w/o x64 emits int32).
// ---------------------------------------------------------------------------
__global__ void prep_kernel(const float* __restrict__ Wq,
                            const float* __restrict__ Wk,
                            const float* __restrict__ Wv,
                            const float* __restrict__ Wo,
                            const void* __restrict__ ei_raw)
{
    int j = threadIdx.x, i = threadIdx.y;
    float m = 0.f, wv = 0.f;
#pragma unroll
    for (int k = 0; k < DIM; k++) {
        m  = fmaf(Wq[i * DIM + k], Wk[j * DIM + k], m);
        wv = fmaf(Wv[i * DIM + k], Wo[k * DIM + j], wv);
    }
    g_M[i * DIM + j] = m;
    g_Wvo[i * DIM + j] = wv;

    if (i == 0) {  // warp 0: parallel sniff + ballot
        long long v = ((const long long*)ei_raw)[j];
        unsigned ok = __ballot_sync(0xffffffffu, v >= 0 && v < N_NODES);
        if (j == 0) g_is64 = (ok == 0xffffffffu);
    }
}

// ---------------------------------------------------------------------------
// Kernel 1: node projections Q' = x@M, VW = x@Wvo.
// 4 nodes/warp; 8 lanes per node; lane owns one float4 of each output row.
// Segmented shfl (width=8): one SHFL broadcasts x[j] in all 4 groups at once.
// Also zero-initializes g_num / g_Z.
// ---------------------------------------------------------------------------
__global__ __launch_bounds__(256) void proj_kernel(const float* __restrict__ x)
{
    int warp = (blockIdx.x * blockDim.x + threadIdx.x) >> 5;
    int lane = threadIdx.x & 31;
    int t = lane & 7;                    // quad index within node
    int node = warp * 4 + (lane >> 3);   // N % 4 == 0: warp-uniform exit
    if (node >= N_NODES) return;

    const float4* X4 = (const float4*)x;
    const float4* M4 = (const float4*)g_M;     // M[j] quad t = M4[j*8+t]
    const float4* W4 = (const float4*)g_Wvo;

    float4 xq = X4[node * 8 + t];              // x[node][4t..4t+3]
    float4 qa = make_float4(0.f, 0.f, 0.f, 0.f);
    float4 va = make_float4(0.f, 0.f, 0.f, 0.f);

#pragma unroll
    for (int j = 0; j < DIM; j++) {
        float comp;
        switch (j & 3) {                       // uniform: component of x[j]
            case 0: comp = xq.x; break;
            case 1: comp = xq.y; break;
            case 2: comp = xq.z; break;
            default: comp = xq.w; break;
        }
        float xj = __shfl_sync(0xffffffffu, comp, j >> 2, 8);  // seg broadcast
        float4 m = M4[j * 8 + t];
        float4 w = W4[j * 8 + t];
        qa.x = fmaf(xj, m.x, qa.x);
        qa.y = fmaf(xj, m.y, qa.y);
        qa.z = fmaf(xj, m.z, qa.z);
        qa.w = fmaf(xj, m.w, qa.w);
        va.x = fmaf(xj, w.x, va.x);
        va.y = fmaf(xj, w.y, va.y);
        va.z = fmaf(xj, w.z, va.z);
        va.w = fmaf(xj, w.w, va.w);
    }

    ((float4*)g_Q)[node * 8 + t]  = qa;
    ((float4*)g_VW)[node * 8 + t] = va;
    ((float4*)g_num)[node * 8 + t] = make_float4(0.f, 0.f, 0.f, 0.f);
    if (t == 0) g_Z[node] = 0.f;
}

// ---------------------------------------------------------------------------
// Kernel 2: edge phase. 8 edges/warp: 4 groups of 8 lanes, 2 edges per group.
//   p = Q'[r] . x[s];  alpha = exp(p * scale)
//   RED: g_Z[r] += alpha;  g_num[r][:] += alpha * VW[s][:]
// ---------------------------------------------------------------------------
__global__ __launch_bounds__(256) void edge_kernel(const float* __restrict__ x,
                                                   const void* __restrict__ ei_raw)
{
    int warp = (blockIdx.x * blockDim.x + threadIdx.x) >> 5;
    int lane = threadIdx.x & 31;
    int l = lane & 7;                     // dim-quad within edge
    int e0 = warp * 8 + (lane >> 3) * 2;  // this group's edge pair (even)
    if (e0 >= E_EDGES) return;            // E % 8 == 0: warp-uniform exit

    int s0, r0, s1, r1;
    if (g_is64) {
        const longlong2* S = (const longlong2*)ei_raw;
        longlong2 sp = S[e0 >> 1];
        longlong2 rp = S[(E_EDGES + e0) >> 1];
        s0 = (int)sp.x; s1 = (int)sp.y;
        r0 = (int)rp.x; r1 = (int)rp.y;
    } else {
        const int2* S = (const int2*)ei_raw;
        int2 sp = S[e0 >> 1];
        int2 rp = S[(E_EDGES + e0) >> 1];
        s0 = sp.x; s1 = sp.y;
        r0 = rp.x; r1 = rp.y;
    }

    const float4* Q4 = (const float4*)g_Q;
    const float4* X4 = (const float4*)x;
    const float4* W4 = (const float4*)g_VW;

    // Issue both edges' gathers before consuming either (2-way MLP).
    float4 q0 = Q4[r0 * 8 + l];
    float4 k0 = X4[s0 * 8 + l];
    float4 q1 = Q4[r1 * 8 + l];
    float4 k1 = X4[s1 * 8 + l];

    float p0 = q0.x * k0.x + q0.y * k0.y + q0.z * k0.z + q0.w * k0.w;
    float p1 = q1.x * k1.x + q1.y * k1.y + q1.z * k1.z + q1.w * k1.w;
#pragma unroll
    for (int off = 1; off <= 4; off <<= 1) {
        p0 += __shfl_xor_sync(0xffffffffu, p0, off);
        p1 += __shfl_xor_sync(0xffffffffu, p1, off);
    }

    const float scale = 0.1767766952966369f;   // 1/sqrt(32)
    float a0 = __expf(p0 * scale);
    float a1 = __expf(p1 * scale);

    float4 v0 = W4[s0 * 8 + l];
    float4 v1 = W4[s1 * 8 + l];

    float* dst0 = g_num + r0 * DIM + l * 4;    // 16B-aligned
    asm volatile("red.global.add.v4.f32 [%0], {%1,%2,%3,%4};"
                 :: "l"(dst0),
                    "f"(a0 * v0.x), "f"(a0 * v0.y),
                    "f"(a0 * v0.z), "f"(a0 * v0.w) : "memory");
    float* dst1 = g_num + r1 * DIM + l * 4;
    asm volatile("red.global.add.v4.f32 [%0], {%1,%2,%3,%4};"
                 :: "l"(dst1),
                    "f"(a1 * v1.x), "f"(a1 * v1.y),
                    "f"(a1 * v1.z), "f"(a1 * v1.w) : "memory");
    if (l == 0) {
        atomicAdd(&g_Z[r0], a0);
        atomicAdd(&g_Z[r1], a1);
    }
}

// ---------------------------------------------------------------------------
// Kernel 3: out = x + num / (Z + 1e-6). Pure elementwise, float4 per thread.
// ---------------------------------------------------------------------------
__global__ __launch_bounds__(256) void out_kernel(
    const float* __restrict__ x,
    float* __restrict__ out)
{
    int t = blockIdx.x * blockDim.x + threadIdx.x;   // one float4 per thread
    if (t >= N_NODES * (DIM / 4)) return;
    int node = t >> 3;                               // 8 quads per node

    float inv = 1.0f / (g_Z[node] + 1e-6f);
    float4 n4 = ((const float4*)g_num)[t];
    float4 x4 = ((const float4*)x)[t];
    float4 o;
    o.x = fmaf(n4.x, inv, x4.x);
    o.y = fmaf(n4.y, inv, x4.y);
    o.z = fmaf(n4.z, inv, x4.z);
    o.w = fmaf(n4.w, inv, x4.w);
    ((float4*)out)[t] = o;
}

// ---------------------------------------------------------------------------
// Launch. Inputs (metadata order): x, edge_index, Wq, Wk, Wv, Wo.
// ---------------------------------------------------------------------------
extern "C" void kernel_launch(void* const* d_in, const int* in_sizes, int n_in,
                              void* d_out, int out_size)
{
    const float* x  = (const float*)d_in[0];
    const void*  ei = d_in[1];
    const float* Wq = (const float*)d_in[2];
    const float* Wk = (const float*)d_in[3];
    const float* Wv = (const float*)d_in[4];
    const float* Wo = (const float*)d_in[5];
    float* out = (float*)d_out;

    const int TPB = 256;
    const int WPB = TPB / 32;

    int proj_warps  = (N_NODES + 3) / 4;                 // 4 nodes per warp
    int proj_blocks = (proj_warps + WPB - 1) / WPB;
    int edge_warps  = (E_EDGES + 7) / 8;                 // 8 edges per warp
    int edge_blocks = (edge_warps + WPB - 1) / WPB;
    int quads       = N_NODES * (DIM / 4);

    prep_kernel<<<1, dim3(32, 32)>>>(Wq, Wk, Wv, Wo, ei);
    proj_kernel<<<proj_blocks, TPB>>>(x);
    edge_kernel<<<edge_blocks, TPB>>>(x, ei);
    out_kernel<<<(quads + TPB - 1) / TPB, TPB>>>(x, out);
}